// round 4
// baseline (speedup 1.0000x reference)
#include <cuda_runtime.h>

#define L 128
#define OUT 65
#define OUT2 (OUT * OUT)      // 4225
#define ROWS_PER_BLK 4
#define BLK_OUT (ROWS_PER_BLK * OUT2)   // 16900 floats, 67600 B (16B-aligned)
#define THREADS 512
#define N_BLOCKS 512          // 2048 rows / 4
#define EPS 1e-6f

__global__ __launch_bounds__(THREADS) void gasf_kernel(const float* __restrict__ x,
                                                       float* __restrict__ out) {
    __shared__ unsigned ball[16];          // one per warp (4 warps per row)
    __shared__ float smn[16], smx[16];
    __shared__ float2 scss[ROWS_PER_BLK][OUT];  // (cos, sin) per row

    const int tid = threadIdx.x;
    const int lane = tid & 31;
    const int wid = tid >> 5;              // 0..15
    const int rin = tid >> 7;              // row within block 0..3
    const int l = tid & 127;               // position within row
    const int row = blockIdx.x * ROWS_PER_BLK + rin;

    const float POS_INF = __int_as_float(0x7f800000);

    // ---- load one element per thread (4 rows x 128) ----
    float v = x[row * L + l];
    unsigned m = __ballot_sync(0xffffffffu, v != 0.0f);
    if (lane == 0) ball[wid] = m;
    __syncthreads();

    // ---- first/last nonzero for this thread's row ----
    const int wb = rin << 2;               // base warp index of this row
    int first = L, last = -1;
    {
        unsigned b0 = ball[wb + 0], b1 = ball[wb + 1], b2 = ball[wb + 2], b3 = ball[wb + 3];
        if (b0)      first = __ffs(b0) - 1;
        else if (b1) first = 32 + __ffs(b1) - 1;
        else if (b2) first = 64 + __ffs(b2) - 1;
        else if (b3) first = 96 + __ffs(b3) - 1;
        if (b3)      last = 96 + 31 - __clz(b3);
        else if (b2) last = 64 + 31 - __clz(b2);
        else if (b1) last = 32 + 31 - __clz(b1);
        else if (b0) last = 31 - __clz(b0);
    }

    bool valid = (l >= first) && (l <= last);   // has_data implied by first<=last
    {
        float mn = valid ? v : POS_INF;
        float mx = valid ? v : -POS_INF;
        #pragma unroll
        for (int off = 16; off; off >>= 1) {
            mn = fminf(mn, __shfl_xor_sync(0xffffffffu, mn, off));
            mx = fmaxf(mx, __shfl_xor_sync(0xffffffffu, mx, off));
        }
        if (lane == 0) { smn[wid] = mn; smx[wid] = mx; }
    }
    __syncthreads();

    float xmin = fminf(fminf(smn[wb], smn[wb + 1]), fminf(smn[wb + 2], smn[wb + 3]));
    float xmax = fmaxf(fmaxf(smx[wb], smx[wb + 1]), fmaxf(smx[wb + 2], smx[wb + 3]));
    xmin = fminf(xmin, 0.0f);                  // inf (all-invalid) -> 0, clamp <= 0
    xmax = fmaxf(xmax, 0.0f);
    float range = fmaxf(xmax - xmin, EPS);

    if (l < OUT) {
        float xn = valid ? (2.0f * (v - xmin) / range - 1.0f) : 0.0f;
        float c = fminf(fmaxf(xn, -1.0f + EPS), 1.0f - EPS);
        float s = sqrtf(fmaxf(1.0f - c * c, 0.0f));
        scss[rin][l] = make_float2(c, s);
    }
    __syncthreads();

    // ---- stream 16900 floats as float4 stores: gasf[r][i][j] = c_i*c_j - s_i*s_j ----
    float4* o4 = (float4*)(out + (size_t)blockIdx.x * BLK_OUT);
    #pragma unroll
    for (int it = 0; it < 9; ++it) {
        int q = tid + it * THREADS;             // float4 index, 0..4224
        if (q < BLK_OUT / 4) {
            float4 res;
            #pragma unroll
            for (int k = 0; k < 4; ++k) {
                int f = q * 4 + k;              // flat index in block output
                int r = f / OUT2;
                int e = f - r * OUT2;
                int i = e / OUT;
                int j = e - i * OUT;
                float2 a = scss[r][i];          // broadcast-heavy LDS.64
                float2 b = scss[r][j];          // stride-1 LDS.64
                ((float*)&res)[k] = fmaf(a.x, b.x, -a.y * b.y);
            }
            o4[q] = res;                        // STG.128, fully coalesced
        }
    }
}

extern "C" void kernel_launch(void* const* d_in, const int* in_sizes, int n_in,
                              void* d_out, int out_size) {
    const float* x = (const float*)d_in[0];
    float* out = (float*)d_out;
    gasf_kernel<<<N_BLOCKS, THREADS>>>(x, out);
}

// round 5
// speedup vs baseline: 1.4974x; 1.4974x over previous
#include <cuda_runtime.h>

#define N_ROWS 2048      // 256 * 8
#define L 128
#define OUT 65
#define OUT2 (OUT * OUT) // 4225
#define THREADS 128
#define EPS 1e-6f

__global__ __launch_bounds__(THREADS) void gasf_kernel(const float* __restrict__ x,
                                                       float* __restrict__ out) {
    __shared__ unsigned ball[4];
    __shared__ float smn[4], smx[4];
    __shared__ float2 scss[OUT];   // (cos, sin) interleaved -> one LDS.64 per operand pair

    const int row = blockIdx.x;               // one (n, c) row per block
    const int tid = threadIdx.x;              // 0..127
    const int lane = tid & 31;
    const int warp = tid >> 5;                // 0..3

    const float POS_INF = __int_as_float(0x7f800000);

    // ---- load 128 elements, one per thread ----
    float v = x[row * L + tid];
    unsigned m = __ballot_sync(0xffffffffu, v != 0.0f);
    if (lane == 0) ball[warp] = m;
    __syncthreads();

    // ---- first/last nonzero position along L ----
    int first = L, last = -1;
    {
        unsigned b0 = ball[0], b1 = ball[1], b2 = ball[2], b3 = ball[3];
        if (b0)      first = __ffs(b0) - 1;
        else if (b1) first = 32 + __ffs(b1) - 1;
        else if (b2) first = 64 + __ffs(b2) - 1;
        else if (b3) first = 96 + __ffs(b3) - 1;
        if (b3)      last = 96 + 31 - __clz(b3);
        else if (b2) last = 64 + 31 - __clz(b2);
        else if (b1) last = 32 + 31 - __clz(b1);
        else if (b0) last = 31 - __clz(b0);
    }

    bool valid = (tid >= first) && (tid <= last);   // has_data implied by first<=last
    {
        float mn = valid ? v : POS_INF;
        float mx = valid ? v : -POS_INF;
        #pragma unroll
        for (int off = 16; off; off >>= 1) {
            mn = fminf(mn, __shfl_xor_sync(0xffffffffu, mn, off));
            mx = fmaxf(mx, __shfl_xor_sync(0xffffffffu, mx, off));
        }
        if (lane == 0) { smn[warp] = mn; smx[warp] = mx; }
    }
    __syncthreads();

    float xmin = fminf(fminf(smn[0], smn[1]), fminf(smn[2], smn[3]));
    float xmax = fmaxf(fmaxf(smx[0], smx[1]), fmaxf(smx[2], smx[3]));
    xmin = fminf(xmin, 0.0f);                  // inf (all-invalid) -> 0, clamp <= 0
    xmax = fmaxf(xmax, 0.0f);
    float range = fmaxf(xmax - xmin, EPS);

    if (tid < OUT) {
        float xn = valid ? (2.0f * (v - xmin) / range - 1.0f) : 0.0f;
        float c = fminf(fmaxf(xn, -1.0f + EPS), 1.0f - EPS);
        float s = sqrtf(fmaxf(1.0f - c * c, 0.0f));
        scss[tid] = make_float2(c, s);
    }
    __syncthreads();

    // ---- write 65x65 tile: gasf[i][j] = c_i*c_j - s_i*s_j ----
    // flat coalesced loop; 33 full iterations of 128 + 1 trailing element.
    // stride 128 = 1*65 + 63  ->  i += 1; j += 63; wrap once.
    float* o = out + (size_t)row * OUT2;
    int i = (tid >= OUT) ? 1 : 0;
    int j = tid - i * OUT;
    #pragma unroll
    for (int it = 0; it < 33; ++it) {
        int idx = tid + it * THREADS;          // always < 4224, no guard
        float2 a = scss[i];                    // broadcast-heavy LDS.64
        float2 b = scss[j];                    // lane-stride-1 LDS.64, conflict-free
        o[idx] = fmaf(a.x, b.x, -a.y * b.y);   // STG.32, fully coalesced
        i += 1; j += 63;
        if (j >= OUT) { j -= OUT; i += 1; }
    }
    if (tid == 0) {                            // final element idx 4224: i=j=64
        float2 a = scss[OUT - 1];
        o[OUT2 - 1] = fmaf(a.x, a.x, -a.y * a.y);
    }
}

extern "C" void kernel_launch(void* const* d_in, const int* in_sizes, int n_in,
                              void* d_out, int out_size) {
    const float* x = (const float*)d_in[0];
    float* out = (float*)d_out;
    gasf_kernel<<<N_ROWS, THREADS>>>(x, out);
}